// round 13
// baseline (speedup 1.0000x reference)
#include <cuda_runtime.h>
#include <cstdint>
#include <math.h>

#define B 96
#define N 512
#define M 512
#define D 32

#define RING 8
#define PF 7
#define SLOT_F 640            // 32 threads * 20 floats (16 data + 4 pad)
#define TSTRIDE_F 20

// Cost matrix scratch (row-major per batch) + per-(batch,chunk) ready flags.
__device__ float g_cost[(size_t)B * N * M];
__device__ unsigned g_flag[B * 4];

// ---------------------------------------------------------------------------
// helpers
// ---------------------------------------------------------------------------
__device__ __forceinline__ unsigned long long pack2f(float x, float y) {
    unsigned long long r;
    asm("mov.b64 %0, {%1, %2};" : "=l"(r) : "f"(x), "f"(y));
    return r;
}
__device__ __forceinline__ void ffma2(unsigned long long& d,
                                      unsigned long long a, unsigned long long b) {
    asm("fma.rn.f32x2 %0, %1, %2, %0;" : "+l"(d) : "l"(a), "l"(b));
}
__device__ __forceinline__ void unpack2f(unsigned long long v, float& x, float& y) {
    asm("mov.b64 {%0, %1}, %2;" : "=f"(x), "=f"(y) : "l"(v));
}
__device__ __forceinline__ void lds_v2u64(unsigned saddr,
                                          unsigned long long& a, unsigned long long& b) {
    asm volatile("ld.shared.v2.u64 {%0, %1}, [%2];" : "=l"(a), "=l"(b) : "r"(saddr));
}
__device__ __forceinline__ float fast_sqrt(float x) {
    float r;
    asm("sqrt.approx.f32 %0, %1;" : "=f"(r) : "f"(x));
    return r;
}
__device__ __forceinline__ void cp_async16(unsigned dst, const float* src) {
    asm volatile("cp.async.cg.shared.global [%0], [%1], 16;\n"
                 :: "r"(dst), "l"(src) : "memory");
}
__device__ __forceinline__ unsigned ld_acquire_gpu(const unsigned* p) {
    unsigned v;
    asm volatile("ld.acquire.gpu.global.b32 %0, [%1];" : "=r"(v) : "l"(p) : "memory");
    return v;
}
__device__ __forceinline__ void red_release_gpu(unsigned* p, unsigned v) {
    asm volatile("red.release.gpu.global.add.u32 [%0], %1;" :: "l"(p), "r"(v) : "memory");
}

// ---------------------------------------------------------------------------
__global__ void zero_flags()
{
    int i = threadIdx.x;
    if (i < B * 4) g_flag[i] = 0u;
}

// ---------------------------------------------------------------------------
// Mega kernel. bid < 96: DTW CTA (warp 0 active, batch=bid).
// bid >= 96: cost CTA — (chunk, half, batch) chunk-major; 256 cols x 128 rows.
// ---------------------------------------------------------------------------
__global__ void __launch_bounds__(256)
mega(const float* __restrict__ seq1, const float* __restrict__ seq2,
     float* __restrict__ out)
{
    __shared__ float sh[RING * SLOT_F];   // 20KB; cost path uses 4224 of it
    const int bid = blockIdx.x;
    const int tid = threadIdx.x;

    if (bid >= B) {
        // =================== COST CTA ===================
        const int idx   = bid - B;
        const int chunk = idx / 192;          // 0..3 (128 rows each)
        const int rem   = idx % 192;
        const int h     = rem / 96;           // column half
        const int bb    = rem % 96;

        const int col = h * 256 + tid;
        const float* s1 = seq1 + (size_t)bb * N * D + (size_t)chunk * 128 * D;
        const float* s2 = seq2 + (size_t)bb * M * D;

        // own seq2 column -> registers (packed f32x2)
        unsigned long long s2p[16];
        float sq2 = 0.f;
        {
            const float4* v = reinterpret_cast<const float4*>(s2 + (size_t)col * D);
#pragma unroll
            for (int q = 0; q < 8; ++q) {
                float4 x = v[q];
                s2p[2 * q]     = pack2f(x.x, x.y);
                s2p[2 * q + 1] = pack2f(x.z, x.w);
                sq2 = fmaf(x.x, x.x, sq2); sq2 = fmaf(x.y, x.y, sq2);
                sq2 = fmaf(x.z, x.z, sq2); sq2 = fmaf(x.w, x.w, sq2);
            }
        }

        // stage 128 seq1 rows (16KB) + sq1
        {
            const float4* src = reinterpret_cast<const float4*>(s1);
            float4* dst = reinterpret_cast<float4*>(sh);
            for (int i = tid; i < 128 * D / 4; i += 256) dst[i] = src[i];
        }
        __syncthreads();
        if (tid < 128) {
            const float* rp = sh + tid * D;
            float acc = 0.f;
#pragma unroll
            for (int k = 0; k < D; ++k) acc = fmaf(rp[k], rp[k], acc);
            sh[4096 + tid] = acc;
        }
        __syncthreads();

        const unsigned sbase = (unsigned)__cvta_generic_to_shared(sh);
        float* outp = g_cost + (size_t)bb * N * M + (size_t)chunk * 128 * M + col;

        for (int i = 0; i < 128; ++i) {
            const unsigned row = sbase + (unsigned)(i * 128);   // 128B per row
            unsigned long long a[16];
#pragma unroll
            for (int q = 0; q < 8; ++q)
                lds_v2u64(row + q * 16, a[2 * q], a[2 * q + 1]);   // broadcast

            unsigned long long acc0 = 0ull, acc1 = 0ull, acc2 = 0ull, acc3 = 0ull;
#pragma unroll
            for (int u = 0; u < 16; u += 4) {
                ffma2(acc0, a[u],     s2p[u]);
                ffma2(acc1, a[u + 1], s2p[u + 1]);
                ffma2(acc2, a[u + 2], s2p[u + 2]);
                ffma2(acc3, a[u + 3], s2p[u + 3]);
            }
            float e0, e1, e2, e3, e4, e5, e6, e7;
            unpack2f(acc0, e0, e1); unpack2f(acc1, e2, e3);
            unpack2f(acc2, e4, e5); unpack2f(acc3, e6, e7);
            float dot = ((e0 + e1) + (e2 + e3)) + ((e4 + e5) + (e6 + e7));
            float dd = sh[4096 + i] + sq2 - 2.f * dot;
            outp[(size_t)i * M] = fast_sqrt(fmaxf(dd, 1e-12f));
        }

        __syncthreads();   // all STGs happen-before the release below
        if (tid == 0) red_release_gpu(&g_flag[bb * 4 + chunk], 1u);
        return;
    }

    // =================== DTW CTA (batch = bid), warp 0 only ===================
    if ((tid >> 5) != 0) return;

    const int b = bid;
    const int t = tid & 31;
    const float INF = INFINITY;

    const float* base = g_cost + (size_t)b * N * M + t * 16;
    const unsigned my_s =
        (unsigned)__cvta_generic_to_shared(sh) + (unsigned)(t * TSTRIDE_F * 4);

    // wait for chunk 0 (rows 0..127) of this batch
    const unsigned* fb = &g_flag[b * 4];
    while (ld_acquire_gpu(fb + 0) < 2u) __nanosleep(128);
    int rdy_rows = 128, next_chunk = 1;

    // prologue: stage rows 0..PF-1
#pragma unroll
    for (int p = 0; p < PF; ++p) {
        const float* src = base + (size_t)p * M;
        unsigned dst = my_s + (unsigned)((p % RING) * SLOT_F * 4);
#pragma unroll
        for (int q = 0; q < 4; ++q) cp_async16(dst + q * 16, src + q * 4);
        asm volatile("cp.async.commit_group;\n" ::: "memory");
    }

    float vprev[16];
#pragma unroll
    for (int k = 0; k < 16; ++k) vprev[k] = INF;
    float diag0 = (t == 0) ? 0.f : INF;
    float lastv = INF;

    const int STEPS = N + 31;   // 543

    for (int s = 0; s < STEPS; ++s) {
        float left0 = __shfl_up_sync(0xffffffffu, lastv, 1);
        if (t == 0) left0 = INF;

        // gate: prefetch target row s+7 must be in a ready chunk (uniform)
        {
            const int need = s + PF;
            if (need < N && need >= rdy_rows) {
                while (ld_acquire_gpu(fb + next_chunk) < 2u) __nanosleep(64);
                rdy_rows += 128;
                ++next_chunk;
            }
        }

        const int r = s - t;

        if (r >= 0 && r + PF < N) {
            const float* src = base + (size_t)(r + PF) * M;
            unsigned dst = my_s + (unsigned)(((r + PF) % RING) * SLOT_F * 4);
#pragma unroll
            for (int q = 0; q < 4; ++q) cp_async16(dst + q * 16, src + q * 4);
        }
        asm volatile("cp.async.commit_group;\n" ::: "memory");
        asm volatile("cp.async.wait_group %0;\n" :: "n"(PF) : "memory");

        if (r >= 0 && r < N) {
            const float4* cp = reinterpret_cast<const float4*>(
                &sh[(r % RING) * SLOT_F + t * TSTRIDE_F]);
            float4 c0 = cp[0], c1 = cp[1], c2 = cp[2], c3 = cp[3];
            float c[16] = { c0.x, c0.y, c0.z, c0.w,
                            c1.x, c1.y, c1.z, c1.w,
                            c2.x, c2.y, c2.z, c2.w,
                            c3.x, c3.y, c3.z, c3.w };

            float P[16];
            P[0] = c[0];
#pragma unroll
            for (int k = 1; k < 16; ++k) P[k] = P[k - 1] + c[k];

            float w[16];
            {
                float m0 = fminf(vprev[0], diag0);
                w[0] = m0;                       // P[-1] = 0
#pragma unroll
                for (int k = 1; k < 16; ++k) {
                    float mk = fminf(vprev[k], vprev[k - 1]);
                    w[k] = mk - P[k - 1];
                }
            }
#pragma unroll
            for (int k = 1; k < 16; ++k) w[k] = fminf(w[k], w[k - 1]);
#pragma unroll
            for (int k = 0; k < 16; ++k)
                vprev[k] = P[k] + fminf(left0, w[k]);

            lastv = vprev[15];
            diag0 = left0;
        }
    }

    if (t == 31) out[b] = lastv;   // D[N-1][M-1]
}

// ---------------------------------------------------------------------------
extern "C" void kernel_launch(void* const* d_in, const int* in_sizes, int n_in,
                              void* d_out, int out_size)
{
    const float* seq1 = (const float*)d_in[0];
    const float* seq2 = (const float*)d_in[1];
    float* out = (float*)d_out;

    zero_flags<<<1, 384>>>();
    mega<<<B + 768, 256>>>(seq1, seq2, out);
}

// round 15
// speedup vs baseline: 1.0107x; 1.0107x over previous
#include <cuda_runtime.h>
#include <cstdint>
#include <math.h>

#define B 96
#define N 512
#define M 512
#define D 32

// Cost matrix scratch: row-major per batch. 96*512*512*4B = 100.7 MB.
__device__ float g_cost[(size_t)B * N * M];

// ---------------------------------------------------------------------------
// helpers
// ---------------------------------------------------------------------------
__device__ __forceinline__ unsigned long long pack2f(float x, float y) {
    unsigned long long r;
    asm("mov.b64 %0, {%1, %2};" : "=l"(r) : "f"(x), "f"(y));
    return r;
}
__device__ __forceinline__ void ffma2(unsigned long long& d,
                                      unsigned long long a, unsigned long long b) {
    asm("fma.rn.f32x2 %0, %1, %2, %0;" : "+l"(d) : "l"(a), "l"(b));
}
__device__ __forceinline__ void unpack2f(unsigned long long v, float& x, float& y) {
    asm("mov.b64 {%0, %1}, %2;" : "=f"(x), "=f"(y) : "l"(v));
}
__device__ __forceinline__ void lds_v2u64(unsigned saddr,
                                          unsigned long long& a, unsigned long long& b) {
    asm volatile("ld.shared.v2.u64 {%0, %1}, [%2];" : "=l"(a), "=l"(b) : "r"(saddr));
}
__device__ __forceinline__ float fast_sqrt(float x) {
    float r;
    asm("sqrt.approx.f32 %0, %1;" : "=f"(r) : "f"(x));
    return r;
}
__device__ __forceinline__ void cp_async16(unsigned dst, const float* src) {
    asm volatile("cp.async.cg.shared.global [%0], [%1], 16;\n"
                 :: "r"(dst), "l"(src) : "memory");
}

// ---------------------------------------------------------------------------
// Kernel 1: pairwise L2 cost, FFMA2, occupancy-2 (64-reg cap, a[8] two-pass).
// grid (96,4), block 512. Thread j owns column j; seq1 chunk staged in smem.
// ---------------------------------------------------------------------------
__global__ void __launch_bounds__(512, 2) cost_kernel(const float* __restrict__ seq1,
                                                      const float* __restrict__ seq2)
{
    const int b = blockIdx.x;
    const int chunk = blockIdx.y;
    const int j = threadIdx.x;

    const float* s1 = seq1 + (size_t)b * N * D;
    const float* s2 = seq2 + (size_t)b * M * D;

    // own seq2 row -> registers, packed into 16 u64 (all 32 floats)
    unsigned long long s2p[16];
    float sq2 = 0.f;
    {
        const float4* s2v = reinterpret_cast<const float4*>(s2 + j * D);
#pragma unroll
        for (int q = 0; q < 8; ++q) {
            float4 v = s2v[q];
            s2p[2 * q]     = pack2f(v.x, v.y);
            s2p[2 * q + 1] = pack2f(v.z, v.w);
            sq2 = fmaf(v.x, v.x, sq2);
            sq2 = fmaf(v.y, v.y, sq2);
            sq2 = fmaf(v.z, v.z, sq2);
            sq2 = fmaf(v.w, v.w, sq2);
        }
    }

    __shared__ float sh_s1[128 * D];   // 16 KB
    __shared__ float sh_sq1[128];

    const int r0 = chunk * 128;

    {
        const float4* src = reinterpret_cast<const float4*>(s1 + r0 * D);
        float4* dst = reinterpret_cast<float4*>(sh_s1);
        for (int idx = j; idx < 128 * D / 4; idx += 512) dst[idx] = src[idx];
    }
    __syncthreads();

    if (j < 128) {
        float acc = 0.f;
#pragma unroll
        for (int k = 0; k < D; ++k) {
            float a = sh_s1[j * D + k];
            acc = fmaf(a, a, acc);
        }
        sh_sq1[j] = acc;
    }
    __syncthreads();

    const unsigned sbase = (unsigned)__cvta_generic_to_shared(sh_s1);
    float* outp = g_cost + (size_t)b * N * M + (size_t)r0 * M + j;

    for (int i = 0; i < 128; ++i) {
        const unsigned row = sbase + (unsigned)(i * 128);   // 128B per row

        unsigned long long a[8];
        unsigned long long acc0 = 0ull, acc1 = 0ull, acc2 = 0ull, acc3 = 0ull;

        // first 64B of the row
#pragma unroll
        for (int q = 0; q < 4; ++q) lds_v2u64(row + q * 16, a[2 * q], a[2 * q + 1]);
        ffma2(acc0, a[0], s2p[0]); ffma2(acc1, a[1], s2p[1]);
        ffma2(acc2, a[2], s2p[2]); ffma2(acc3, a[3], s2p[3]);
        ffma2(acc0, a[4], s2p[4]); ffma2(acc1, a[5], s2p[5]);
        ffma2(acc2, a[6], s2p[6]); ffma2(acc3, a[7], s2p[7]);

        // second 64B of the row
#pragma unroll
        for (int q = 0; q < 4; ++q) lds_v2u64(row + 64 + q * 16, a[2 * q], a[2 * q + 1]);
        ffma2(acc0, a[0], s2p[8]);  ffma2(acc1, a[1], s2p[9]);
        ffma2(acc2, a[2], s2p[10]); ffma2(acc3, a[3], s2p[11]);
        ffma2(acc0, a[4], s2p[12]); ffma2(acc1, a[5], s2p[13]);
        ffma2(acc2, a[6], s2p[14]); ffma2(acc3, a[7], s2p[15]);

        float e0, e1, e2, e3, e4, e5, e6, e7;
        unpack2f(acc0, e0, e1); unpack2f(acc1, e2, e3);
        unpack2f(acc2, e4, e5); unpack2f(acc3, e6, e7);
        float dot = ((e0 + e1) + (e2 + e3)) + ((e4 + e5) + (e6 + e7));

        float dd = sh_sq1[i] + sq2 - 2.f * dot;
        outp[(size_t)i * M] = fast_sqrt(fmaxf(dd, 1e-12f));
    }
}

// ---------------------------------------------------------------------------
// Kernel 2: DTW wavefront, cp.async ring (PF=7) + P prefetched 2 steps ahead.
// Read distance from ring = 2 rows ahead of compute -> wait_group 5.
// Inter-step chain: shfl -> w -> prefix-min -> v  (P off the chain).
// ---------------------------------------------------------------------------
#define RING 8
#define PF 7
#define SLOT_F 640            // 32 threads * 20 floats (16 data + 4 pad)
#define TSTRIDE_F 20

__global__ void __launch_bounds__(32) dtw_kernel(float* __restrict__ out)
{
    const int b = blockIdx.x;
    const int t = threadIdx.x;
    const float INF = INFINITY;

    const float* base = g_cost + (size_t)b * N * M + t * 16;

    __shared__ float ring[RING * SLOT_F];   // 20 KB
    const unsigned my_s =
        (unsigned)__cvta_generic_to_shared(ring) + (unsigned)(t * TSTRIDE_F * 4);

    // prologue: stage rows 0..PF-1, one commit group per row
#pragma unroll
    for (int p = 0; p < PF; ++p) {
        const float* src = base + (size_t)p * M;
        unsigned dst = my_s + (unsigned)((p % RING) * SLOT_F * 4);
#pragma unroll
        for (int q = 0; q < 4; ++q) cp_async16(dst + q * 16, src + q * 4);
        asm volatile("cp.async.commit_group;\n" ::: "memory");
    }
    // first 2 groups (rows 0,1) done:
    asm volatile("cp.async.wait_group 5;\n" ::: "memory");

    // P buffers for steps s (PA) and s+1 (PB)
    float PA[16], PB[16];
    auto loadP = [&](float* P, int row) {
        const float4* cp = reinterpret_cast<const float4*>(
            &ring[(row % RING) * SLOT_F + t * TSTRIDE_F]);
        float4 c0 = cp[0], c1 = cp[1], c2 = cp[2], c3 = cp[3];
        float c[16] = { c0.x, c0.y, c0.z, c0.w, c1.x, c1.y, c1.z, c1.w,
                        c2.x, c2.y, c2.z, c2.w, c3.x, c3.y, c3.z, c3.w };
        P[0] = c[0];
#pragma unroll
        for (int k = 1; k < 16; ++k) P[k] = P[k - 1] + c[k];
    };
    {
        int r0 = 0 - t; if (r0 < 0) r0 = 0;          // row for step 0
        int r1 = 1 - t; if (r1 < 0) r1 = 0;          // row for step 1
        loadP(PA, r0);
        loadP(PB, r1);
    }

    float vprev[16];
#pragma unroll
    for (int k = 0; k < 16; ++k) vprev[k] = INF;
    float diag0 = (t == 0) ? 0.f : INF;
    float lastv = INF;

    auto cstep = [&](int s, float* P) {
        float left0 = __shfl_up_sync(0xffffffffu, lastv, 1);
        if (t == 0) left0 = INF;

        const int r = s - t;
        if (r >= 0 && r < N) {
            float w[16];
            w[0] = fminf(vprev[0], diag0);           // P[-1] = 0
#pragma unroll
            for (int k = 1; k < 16; ++k)
                w[k] = fminf(vprev[k], vprev[k - 1]) - P[k - 1];
#pragma unroll
            for (int k = 1; k < 16; ++k) w[k] = fminf(w[k], w[k - 1]);
#pragma unroll
            for (int k = 0; k < 16; ++k)
                vprev[k] = P[k] + fminf(left0, w[k]);
            lastv = vprev[15];
            diag0 = left0;
        }

        // future memory work (off the inter-step chain):
        if (r >= 0 && r + PF < N) {
            const float* src = base + (size_t)(r + PF) * M;
            unsigned dst = my_s + (unsigned)(((r + PF) % RING) * SLOT_F * 4);
#pragma unroll
            for (int q = 0; q < 4; ++q) cp_async16(dst + q * 16, src + q * 4);
        }
        asm volatile("cp.async.commit_group;\n" ::: "memory");
        // groups through row s+2 are done after this:
        asm volatile("cp.async.wait_group 5;\n" ::: "memory");

        int rn = s + 2 - t;                          // row for step s+2
        if (rn < 0) rn = 0;
        if (rn > N - 1) rn = N - 1;
        loadP(P, rn);                                 // refill same buffer
    };

    // 544 steps (even count; step 543 is all-inactive, harmless)
    for (int s = 0; s < 544; s += 2) {
        cstep(s, PA);
        cstep(s + 1, PB);
    }

    if (t == 31) out[b] = lastv;   // D[N-1][M-1]
}

// ---------------------------------------------------------------------------
extern "C" void kernel_launch(void* const* d_in, const int* in_sizes, int n_in,
                              void* d_out, int out_size)
{
    const float* seq1 = (const float*)d_in[0];
    const float* seq2 = (const float*)d_in[1];
    float* out = (float*)d_out;

    dim3 g1(B, 4);
    cost_kernel<<<g1, 512>>>(seq1, seq2);
    dtw_kernel<<<B, 32>>>(out);
}

// round 16
// speedup vs baseline: 1.0957x; 1.0840x over previous
#include <cuda_runtime.h>
#include <cstdint>
#include <math.h>

#define B 96
#define N 512
#define M 512
#define D 32

// Cost matrix scratch: row-major per batch. 96*512*512*4B = 100.7 MB.
__device__ float g_cost[(size_t)B * N * M];

// ---------------------------------------------------------------------------
// helpers
// ---------------------------------------------------------------------------
__device__ __forceinline__ unsigned long long pack2f(float x, float y) {
    unsigned long long r;
    asm("mov.b64 %0, {%1, %2};" : "=l"(r) : "f"(x), "f"(y));
    return r;
}
__device__ __forceinline__ void ffma2(unsigned long long& d,
                                      unsigned long long a, unsigned long long b) {
    asm("fma.rn.f32x2 %0, %1, %2, %0;" : "+l"(d) : "l"(a), "l"(b));
}
__device__ __forceinline__ void unpack2f(unsigned long long v, float& x, float& y) {
    asm("mov.b64 {%0, %1}, %2;" : "=f"(x), "=f"(y) : "l"(v));
}
__device__ __forceinline__ void lds_v2u64(unsigned saddr,
                                          unsigned long long& a, unsigned long long& b) {
    asm volatile("ld.shared.v2.u64 {%0, %1}, [%2];" : "=l"(a), "=l"(b) : "r"(saddr));
}
__device__ __forceinline__ float fast_sqrt(float x) {
    float r;
    asm("sqrt.approx.f32 %0, %1;" : "=f"(r) : "f"(x));
    return r;
}
__device__ __forceinline__ void cp_async16(unsigned dst, const float* src) {
    asm volatile("cp.async.cg.shared.global [%0], [%1], 16;\n"
                 :: "r"(dst), "l"(src) : "memory");
}

// Dummy kernel: shifts launch parity so ncu (-s 5 -c 1) captures cost_kernel.
__global__ void dummy_k() {}

// ---------------------------------------------------------------------------
// Kernel 1: pairwise L2 cost, FFMA2. 256 threads, occupancy-3 (85-reg cap,
// no spills: s2p 32 + a 16 + acc 8 + misc ~20 = ~76 live).
// grid (96, 4, 2): y = 128-row chunk, z = 256-column half.
// Thread owns column z*256+tid; seq1 chunk staged in smem (broadcast reads).
// ---------------------------------------------------------------------------
__global__ void __launch_bounds__(256, 3) cost_kernel(const float* __restrict__ seq1,
                                                      const float* __restrict__ seq2)
{
    const int b = blockIdx.x;
    const int chunk = blockIdx.y;
    const int j = blockIdx.z * 256 + threadIdx.x;
    const int tid = threadIdx.x;

    const float* s1 = seq1 + (size_t)b * N * D;
    const float* s2 = seq2 + (size_t)b * M * D;

    // own seq2 row -> registers, packed into 16 u64 (all 32 floats)
    unsigned long long s2p[16];
    float sq2 = 0.f;
    {
        const float4* s2v = reinterpret_cast<const float4*>(s2 + j * D);
#pragma unroll
        for (int q = 0; q < 8; ++q) {
            float4 v = s2v[q];
            s2p[2 * q]     = pack2f(v.x, v.y);
            s2p[2 * q + 1] = pack2f(v.z, v.w);
            sq2 = fmaf(v.x, v.x, sq2);
            sq2 = fmaf(v.y, v.y, sq2);
            sq2 = fmaf(v.z, v.z, sq2);
            sq2 = fmaf(v.w, v.w, sq2);
        }
    }

    __shared__ float sh_s1[128 * D];   // 16 KB
    __shared__ float sh_sq1[128];

    const int r0 = chunk * 128;

    {
        const float4* src = reinterpret_cast<const float4*>(s1 + r0 * D);
        float4* dst = reinterpret_cast<float4*>(sh_s1);
        for (int idx = tid; idx < 128 * D / 4; idx += 256) dst[idx] = src[idx];
    }
    __syncthreads();

    if (tid < 128) {
        float acc = 0.f;
#pragma unroll
        for (int k = 0; k < D; ++k) {
            float a = sh_s1[tid * D + k];
            acc = fmaf(a, a, acc);
        }
        sh_sq1[tid] = acc;
    }
    __syncthreads();

    const unsigned sbase = (unsigned)__cvta_generic_to_shared(sh_s1);
    float* outp = g_cost + (size_t)b * N * M + (size_t)r0 * M + j;

    for (int i = 0; i < 128; ++i) {
        const unsigned row = sbase + (unsigned)(i * 128);   // 128B per row

        unsigned long long a[8];
        unsigned long long acc0 = 0ull, acc1 = 0ull, acc2 = 0ull, acc3 = 0ull;

        // first 64B of the row
#pragma unroll
        for (int q = 0; q < 4; ++q) lds_v2u64(row + q * 16, a[2 * q], a[2 * q + 1]);
        ffma2(acc0, a[0], s2p[0]); ffma2(acc1, a[1], s2p[1]);
        ffma2(acc2, a[2], s2p[2]); ffma2(acc3, a[3], s2p[3]);
        ffma2(acc0, a[4], s2p[4]); ffma2(acc1, a[5], s2p[5]);
        ffma2(acc2, a[6], s2p[6]); ffma2(acc3, a[7], s2p[7]);

        // second 64B of the row
#pragma unroll
        for (int q = 0; q < 4; ++q) lds_v2u64(row + 64 + q * 16, a[2 * q], a[2 * q + 1]);
        ffma2(acc0, a[0], s2p[8]);  ffma2(acc1, a[1], s2p[9]);
        ffma2(acc2, a[2], s2p[10]); ffma2(acc3, a[3], s2p[11]);
        ffma2(acc0, a[4], s2p[12]); ffma2(acc1, a[5], s2p[13]);
        ffma2(acc2, a[6], s2p[14]); ffma2(acc3, a[7], s2p[15]);

        float e0, e1, e2, e3, e4, e5, e6, e7;
        unpack2f(acc0, e0, e1); unpack2f(acc1, e2, e3);
        unpack2f(acc2, e4, e5); unpack2f(acc3, e6, e7);
        float dot = ((e0 + e1) + (e2 + e3)) + ((e4 + e5) + (e6 + e7));

        float dd = sh_sq1[i] + sq2 - 2.f * dot;
        outp[(size_t)i * M] = fast_sqrt(fmaxf(dd, 1e-12f));
    }
}

// ---------------------------------------------------------------------------
// Kernel 2: DTW wavefront (exact R6 form — 75.3us measured).
// cp.async ring PF=7; min-plus prefix restructure computed inline.
// ---------------------------------------------------------------------------
#define RING 8
#define PF 7
#define SLOT_F 640            // 32 threads * 20 floats (16 data + 4 pad)
#define TSTRIDE_F 20

__global__ void __launch_bounds__(32) dtw_kernel(float* __restrict__ out)
{
    const int b = blockIdx.x;
    const int t = threadIdx.x;
    const float INF = INFINITY;

    const float* base = g_cost + (size_t)b * N * M + t * 16;

    __shared__ float ring[RING * SLOT_F];   // 20 KB
    const unsigned my_s =
        (unsigned)__cvta_generic_to_shared(ring) + (unsigned)(t * TSTRIDE_F * 4);

    // prologue: stage rows 0..PF-1
#pragma unroll
    for (int p = 0; p < PF; ++p) {
        const float* src = base + (size_t)p * M;
        unsigned dst = my_s + (unsigned)((p % RING) * SLOT_F * 4);
#pragma unroll
        for (int q = 0; q < 4; ++q) cp_async16(dst + q * 16, src + q * 4);
        asm volatile("cp.async.commit_group;\n" ::: "memory");
    }

    float vprev[16];
#pragma unroll
    for (int k = 0; k < 16; ++k) vprev[k] = INF;

    float diag0 = (t == 0) ? 0.f : INF;   // D[r-1][j0-1]
    float lastv = INF;

    const int STEPS = N + 31;   // 543

    for (int s = 0; s < STEPS; ++s) {
        float left0 = __shfl_up_sync(0xffffffffu, lastv, 1);
        if (t == 0) left0 = INF;

        const int r = s - t;

        if (r >= 0 && r + PF < N) {
            const float* src = base + (size_t)(r + PF) * M;
            unsigned dst = my_s + (unsigned)(((r + PF) % RING) * SLOT_F * 4);
#pragma unroll
            for (int q = 0; q < 4; ++q) cp_async16(dst + q * 16, src + q * 4);
        }
        asm volatile("cp.async.commit_group;\n" ::: "memory");
        asm volatile("cp.async.wait_group %0;\n" :: "n"(PF) : "memory");

        if (r >= 0 && r < N) {
            const float4* cp = reinterpret_cast<const float4*>(
                &ring[(r % RING) * SLOT_F + t * TSTRIDE_F]);
            float4 c0 = cp[0], c1 = cp[1], c2 = cp[2], c3 = cp[3];
            float c[16] = { c0.x, c0.y, c0.z, c0.w,
                            c1.x, c1.y, c1.z, c1.w,
                            c2.x, c2.y, c2.z, c2.w,
                            c3.x, c3.y, c3.z, c3.w };

            // P[k] = prefix sum of c (serial, off the inter-step chain)
            float P[16];
            P[0] = c[0];
#pragma unroll
            for (int k = 1; k < 16; ++k) P[k] = P[k - 1] + c[k];

            // m[k] = min(up, diag) — parallel;  w[k] = m[k] - P[k-1]
            float w[16];
            {
                float m0 = fminf(vprev[0], diag0);
                w[0] = m0;                       // P[-1] = 0
#pragma unroll
                for (int k = 1; k < 16; ++k) {
                    float mk = fminf(vprev[k], vprev[k - 1]);
                    w[k] = mk - P[k - 1];
                }
            }

            // Wmin[k] = prefix-min of w (serial, off-chain)
#pragma unroll
            for (int k = 1; k < 16; ++k) w[k] = fminf(w[k], w[k - 1]);

            // v[k] = P[k] + min(left0, Wmin[k]) — left0 only enters here
#pragma unroll
            for (int k = 0; k < 16; ++k)
                vprev[k] = P[k] + fminf(left0, w[k]);

            lastv = vprev[15];
            diag0 = left0;
        }
    }

    if (t == 31) out[b] = lastv;   // D[N-1][M-1]
}

// ---------------------------------------------------------------------------
extern "C" void kernel_launch(void* const* d_in, const int* in_sizes, int n_in,
                              void* d_out, int out_size)
{
    const float* seq1 = (const float*)d_in[0];
    const float* seq2 = (const float*)d_in[1];
    float* out = (float*)d_out;

    // Launch order (4/call) puts cost_kernel at global launch #5 for ncu -s 5.
    dummy_k<<<1, 32>>>();
    dim3 g1(B, 4, 2);
    cost_kernel<<<g1, 256>>>(seq1, seq2);
    dtw_kernel<<<B, 32>>>(out);
    dummy_k<<<1, 32>>>();
}